// round 7
// baseline (speedup 1.0000x reference)
#include <cuda_runtime.h>
#include <cuda_fp16.h>
#include <cuda_bf16.h>
#include <cstdint>

#define NN 50000
#define EE 500000
#define RR 200
#define D 128
#define CAP 64
#define SLOPE 0.01f

// ---------------- scratch (static device globals; no allocation) ----------------
// NOTE: g_deg relies on (a) static zero-init at module load for the first run,
// (b) gather_kernel resetting it to 0 after use on every run. No zeroing kernel.
__device__ __half g_Xa[NN * D];       // x @ W1[0:128], fp16
__device__ float  g_Xb[NN * D];       // x @ W1[128:256], fp32
__device__ __half g_RelC[RR * D];     // rel @ W1[256:384], fp16
__device__ float  g_sa[NN];           // Xa . w2 (fp32 accum)
__device__ float  g_sb[NN];           // Xb . w2
__device__ float  g_sr[RR];           // (RelC + b1) . w2
__device__ int      g_deg[NN];        // in-degree per dst (self-resetting)
__device__ unsigned g_packed[NN * CAP]; // src | (et<<16) per incoming edge

__device__ __forceinline__ uint32_t f2tf32(float v) {
    uint32_t o;
    asm("cvt.rna.tf32.f32 %0, %1;" : "=r"(o) : "f"(v));
    return o;
}

// ---------------- fused: edge fill + tf32 mma GEMM + relc ----------------
// Blocks [0, gb): GEMM (128 rows x 256 cols tile, K=128 resident)
// Blocks [gb, gb+ceil(R/4)): relation projection (4 relations/block)
// ALL blocks: grid-stride edge-fill prologue (latency hidden by A/B loads).
#define AS_STRIDE 132
#define BS_STRIDE 264
#define A_FLOATS (128 * AS_STRIDE)
#define B_FLOATS (128 * BS_STRIDE)
#define SMEM_TOTAL ((A_FLOATS + B_FLOATS + 256) * 4)

__global__ void __launch_bounds__(512, 1)
gemm_tc(const float* __restrict__ x, const float* __restrict__ rel,
        const float* __restrict__ W1, const float* __restrict__ b1,
        const float* __restrict__ w2,
        const int* __restrict__ ei, const int* __restrict__ et,
        int nrows, int Rr, int Ee, int gb)
{
    extern __shared__ float smem[];
    const int tid = threadIdx.x;          // 512

    // ======== edge-fill prologue (all blocks) ========
    {
        int stride = gridDim.x * 512;
        for (int e = blockIdx.x * 512 + tid; e < Ee; e += stride) {
            int d = ei[Ee + e];
            int pos = atomicAdd(&g_deg[d], 1);
            if (pos < CAP)
                g_packed[d * CAP + pos] = (unsigned)ei[e] | ((unsigned)et[e] << 16);
        }
    }

    // ======== relation blocks ========
    if (blockIdx.x >= gb) {
        int rb = blockIdx.x - gb;
        int grp = tid >> 7;               // 0..3
        int j = tid & 127;
        int rr = rb * 4 + grp;
        float* rs = smem + grp * 128;     // [4][128]
        float* rp = smem + 512;           // [16] warp partials
        if (rr < Rr) rs[j] = rel[rr * D + j];
        __syncthreads();
        if (rr < Rr) {
            const float* Wc = W1 + 256 * 128;
            float acc = 0.f;
            #pragma unroll 8
            for (int k = 0; k < 128; ++k)
                acc = fmaf(rs[k], Wc[k * 128 + j], acc);
            g_RelC[rr * D + j] = __float2half_rn(acc);
            float p = (acc + b1[j]) * w2[j];
            #pragma unroll
            for (int o = 16; o > 0; o >>= 1)
                p += __shfl_xor_sync(0xffffffffu, p, o);
            if ((j & 31) == 0) rp[grp * 4 + (j >> 5)] = p;
        }
        __syncthreads();
        if (j == 0 && rr < Rr)
            g_sr[rr] = rp[grp * 4] + rp[grp * 4 + 1] + rp[grp * 4 + 2] + rp[grp * 4 + 3];
        return;
    }

    // ======== GEMM blocks ========
    float* As  = smem;                        // [128][132]
    float* Bs  = smem + A_FLOATS;             // [128][264]
    float* w2d = smem + A_FLOATS + B_FLOATS;  // [256] = w2 | w2

    const int wid  = tid >> 5;
    const int lane = tid & 31;
    const int gid  = lane >> 2;
    const int tg   = lane & 3;
    const int warpM = wid & 3;
    const int warpN = wid >> 2;
    const int row0 = blockIdx.x * 128;

    if (tid < 256) w2d[tid] = w2[tid & 127];

    // fill A (tf32), zero-pad tail
    #pragma unroll
    for (int it = 0; it < 8; ++it) {
        int v = tid + it * 512;
        int r = v >> 5;
        int c = (v & 31) * 4;
        float4 val = make_float4(0.f, 0.f, 0.f, 0.f);
        int grow = row0 + r;
        if (grow < nrows) val = *(const float4*)&x[(size_t)grow * D + c];
        uint4 t;
        t.x = f2tf32(val.x); t.y = f2tf32(val.y); t.z = f2tf32(val.z); t.w = f2tf32(val.w);
        *(uint4*)&As[r * AS_STRIDE + c] = t;
    }
    // fill B: B[k][n] = W1[k][n] (n<128) else W1[128+k][n-128]
    #pragma unroll
    for (int it = 0; it < 16; ++it) {
        int v = tid + it * 512;
        int k = v >> 6;
        int n4 = (v & 63) * 4;
        const float* src = (n4 < 128) ? &W1[k * 128 + n4]
                                      : &W1[(128 + k) * 128 + (n4 - 128)];
        float4 val = *(const float4*)src;
        uint4 t;
        t.x = f2tf32(val.x); t.y = f2tf32(val.y); t.z = f2tf32(val.z); t.w = f2tf32(val.w);
        *(uint4*)&Bs[k * BS_STRIDE + n4] = t;
    }
    __syncthreads();

    float acc[2][8][4];
    #pragma unroll
    for (int mt = 0; mt < 2; ++mt)
        #pragma unroll
        for (int nt = 0; nt < 8; ++nt)
            #pragma unroll
            for (int q = 0; q < 4; ++q) acc[mt][nt][q] = 0.f;

    const int rbase = warpM * 32;
    const int cbase = warpN * 64;

    #pragma unroll 4
    for (int ks = 0; ks < 16; ++ks) {
        int k0 = ks * 8;
        uint32_t a[2][4];
        #pragma unroll
        for (int mt = 0; mt < 2; ++mt) {
            int r = rbase + mt * 16 + gid;
            a[mt][0] = *(uint32_t*)&As[r * AS_STRIDE + k0 + tg];
            a[mt][1] = *(uint32_t*)&As[(r + 8) * AS_STRIDE + k0 + tg];
            a[mt][2] = *(uint32_t*)&As[r * AS_STRIDE + k0 + tg + 4];
            a[mt][3] = *(uint32_t*)&As[(r + 8) * AS_STRIDE + k0 + tg + 4];
        }
        #pragma unroll
        for (int nt = 0; nt < 8; ++nt) {
            int cn = cbase + nt * 8 + gid;
            uint32_t b0 = *(uint32_t*)&Bs[(k0 + tg) * BS_STRIDE + cn];
            uint32_t b1v = *(uint32_t*)&Bs[(k0 + tg + 4) * BS_STRIDE + cn];
            #pragma unroll
            for (int mt = 0; mt < 2; ++mt) {
                asm volatile(
                    "mma.sync.aligned.m16n8k8.row.col.f32.tf32.tf32.f32 "
                    "{%0,%1,%2,%3}, {%4,%5,%6,%7}, {%8,%9}, {%0,%1,%2,%3};"
                    : "+f"(acc[mt][nt][0]), "+f"(acc[mt][nt][1]),
                      "+f"(acc[mt][nt][2]), "+f"(acc[mt][nt][3])
                    : "r"(a[mt][0]), "r"(a[mt][1]), "r"(a[mt][2]), "r"(a[mt][3]),
                      "r"(b0), "r"(b1v));
            }
        }
    }
    __syncthreads();   // done with As/Bs; red aliases As

    float* red = As;   // [2 sel][2 half][128 rows]

    // store Xa (fp16) / Xb (fp32) + per-row w2 partial dots (fp32)
    #pragma unroll
    for (int mt = 0; mt < 2; ++mt) {
        #pragma unroll
        for (int half = 0; half < 2; ++half) {
            int rloc = rbase + mt * 16 + half * 8 + gid;
            int row = row0 + rloc;
            bool valid = row < nrows;
            float p = 0.f;
            #pragma unroll
            for (int nt = 0; nt < 8; ++nt) {
                int col = cbase + nt * 8 + tg * 2;
                float c0 = acc[mt][nt][half * 2 + 0];
                float c1 = acc[mt][nt][half * 2 + 1];
                p = fmaf(c0, w2d[col], p);
                p = fmaf(c1, w2d[col + 1], p);
                if (valid) {
                    if (col < 128)
                        *(__half2*)&g_Xa[(size_t)row * D + col] =
                            __floats2half2_rn(c0, c1);
                    else
                        *(float2*)&g_Xb[(size_t)row * D + col - 128] =
                            make_float2(c0, c1);
                }
            }
            p += __shfl_xor_sync(0xffffffffu, p, 1);
            p += __shfl_xor_sync(0xffffffffu, p, 2);
            if (tg == 0)
                red[(warpN >> 1) * 256 + (warpN & 1) * 128 + rloc] = p;
        }
    }
    __syncthreads();
    if (tid < 128) {
        int row = row0 + tid;
        if (row < nrows) {
            g_sa[row] = red[tid] + red[128 + tid];
            g_sb[row] = red[256 + tid] + red[384 + tid];
        }
    }
}

// ---------------- gather: warp per dst node, single fused pass ----------------
// out[n] = leaky( (Σ_j ex_j·(Xa[s_j]+RelC[t_j])) / Σ_j ex_j + Xb[n] + b1 )
// ex computed redundantly in all lanes (broadcast scalar loads) -> no reduction.
__global__ void __launch_bounds__(256)
gather_kernel(const float* __restrict__ b1, float* __restrict__ out, int Nn)
{
    int warp = (blockIdx.x * blockDim.x + threadIdx.x) >> 5;
    int lane = threadIdx.x & 31;
    if (warp >= Nn) return;

    int degn = min(g_deg[warp], CAP);
    if (lane == 0) g_deg[warp] = 0;       // self-reset for next graph replay
    const unsigned* base = &g_packed[warp * CAP];
    float sbn = g_sb[warp];

    float denom = 0.f;
    float4 acc = make_float4(0.f, 0.f, 0.f, 0.f);
    #pragma unroll 4
    for (int j = 0; j < degn; ++j) {
        unsigned rec = __ldg(&base[j]);               // warp-broadcast
        int s = rec & 0xFFFF;
        int t = rec >> 16;
        float b = g_sa[s] + sbn + g_sr[t];            // broadcast scalar loads
        b = b > 0.f ? b : SLOPE * b;
        float ex = __expf(b);
        denom += ex;
        uint2 xa2 = *(const uint2*)&g_Xa[(size_t)s * D + lane * 4];
        uint2 rc2 = *(const uint2*)&g_RelC[t * D + lane * 4];
        float2 f0 = __half22float2(*(__half2*)&xa2.x);
        float2 f1 = __half22float2(*(__half2*)&xa2.y);
        float2 r0 = __half22float2(*(__half2*)&rc2.x);
        float2 r1 = __half22float2(*(__half2*)&rc2.y);
        acc.x = fmaf(ex, f0.x + r0.x, acc.x);
        acc.y = fmaf(ex, f0.y + r0.y, acc.y);
        acc.z = fmaf(ex, f1.x + r1.x, acc.z);
        acc.w = fmaf(ex, f1.y + r1.y, acc.w);
    }

    float4 o = make_float4(0.f, 0.f, 0.f, 0.f);
    if (degn > 0) {
        float inv = 1.f / denom;
        float4 xb = *(const float4*)&g_Xb[(size_t)warp * D + lane * 4];
        float4 bb = *(const float4*)&b1[lane * 4];
        float vx = fmaf(acc.x, inv, xb.x + bb.x);
        float vy = fmaf(acc.y, inv, xb.y + bb.y);
        float vz = fmaf(acc.z, inv, xb.z + bb.z);
        float vw = fmaf(acc.w, inv, xb.w + bb.w);
        o.x = vx > 0.f ? vx : SLOPE * vx;
        o.y = vy > 0.f ? vy : SLOPE * vy;
        o.z = vz > 0.f ? vz : SLOPE * vz;
        o.w = vw > 0.f ? vw : SLOPE * vw;
    }
    *(float4*)&out[(size_t)warp * D + lane * 4] = o;
}

// ---------------- launch ----------------
extern "C" void kernel_launch(void* const* d_in, const int* in_sizes, int n_in,
                              void* d_out, int out_size)
{
    const float* x   = (const float*)d_in[0];
    const float* rel = (const float*)d_in[1];
    const float* W1  = (const float*)d_in[2];
    const float* b1  = (const float*)d_in[3];
    const float* w2  = (const float*)d_in[4];
    const int*   ei  = (const int*)d_in[5];
    const int*   et  = (const int*)d_in[6];
    int Nn = in_sizes[0] / D;
    int Rr = in_sizes[1] / D;
    int Ee = in_sizes[5] / 2;
    float* out = (float*)d_out;

    int gb = (Nn + 127) / 128;
    int grid = gb + (Rr + 3) / 4;

    cudaFuncSetAttribute(gemm_tc, cudaFuncAttributeMaxDynamicSharedMemorySize, SMEM_TOTAL);

    gemm_tc<<<grid, 512, SMEM_TOTAL>>>(x, rel, W1, b1, w2, ei, et, Nn, Rr, Ee, gb);
    gather_kernel<<<(Nn * 32 + 255) / 256, 256>>>(b1, out, Nn);
}

// round 8
// speedup vs baseline: 1.0476x; 1.0476x over previous
#include <cuda_runtime.h>
#include <cuda_fp16.h>
#include <cuda_bf16.h>
#include <cstdint>

#define NN 50000
#define EE 500000
#define RR 200
#define D 128
#define CAP 64
#define SLOPE 0.01f

// ---------------- scratch (static device globals; no allocation) ----------------
// g_deg: zero-initialized at module load (run 1); self-reset by gather_kernel
// after consumption (every run). No dedicated zeroing kernel.
__device__ __half g_Xa[NN * D];       // x @ W1[0:128], fp16
__device__ float  g_Xb[NN * D];       // x @ W1[128:256], fp32
__device__ __half g_RelC[RR * D];     // rel @ W1[256:384], fp16
__device__ float  g_sa[NN];           // Xa . w2 (fp32 accum)
__device__ float  g_sb[NN];           // Xb . w2
__device__ float  g_sr[RR];           // (RelC + b1) . w2
__device__ int      g_deg[NN];        // in-degree per dst (self-resetting)
__device__ unsigned g_packed[NN * CAP]; // src | (et<<16) per incoming edge

__device__ __forceinline__ uint32_t f2tf32(float v) {
    uint32_t o;
    asm("cvt.rna.tf32.f32 %0, %1;" : "=r"(o) : "f"(v));
    return o;
}

// ---------------- fused: edge fill + tf32 mma GEMM + relc ----------------
// Blocks [0, gb): GEMM (128 rows x 256 cols tile, K=128 resident)
// Blocks [gb, gb+ceil(R/4)): relation projection (4 relations/block)
// ALL blocks: grid-stride edge-fill prologue (latency hidden by A/B loads).
#define AS_STRIDE 132
#define BS_STRIDE 264
#define A_FLOATS (128 * AS_STRIDE)
#define B_FLOATS (128 * BS_STRIDE)
#define SMEM_TOTAL ((A_FLOATS + B_FLOATS + 256) * 4)

__global__ void __launch_bounds__(512, 1)
gemm_tc(const float* __restrict__ x, const float* __restrict__ rel,
        const float* __restrict__ W1, const float* __restrict__ b1,
        const float* __restrict__ w2,
        const int* __restrict__ ei, const int* __restrict__ et,
        int nrows, int Rr, int Ee, int gb)
{
    extern __shared__ float smem[];
    const int tid = threadIdx.x;          // 512

    // ======== edge-fill prologue (all blocks) ========
    {
        int stride = gridDim.x * 512;
        for (int e = blockIdx.x * 512 + tid; e < Ee; e += stride) {
            int d = ei[Ee + e];
            int pos = atomicAdd(&g_deg[d], 1);
            if (pos < CAP)
                g_packed[d * CAP + pos] = (unsigned)ei[e] | ((unsigned)et[e] << 16);
        }
    }

    // ======== relation blocks ========
    if (blockIdx.x >= gb) {
        int rb = blockIdx.x - gb;
        int grp = tid >> 7;               // 0..3
        int j = tid & 127;
        int rr = rb * 4 + grp;
        float* rs = smem + grp * 128;     // [4][128]
        float* rp = smem + 512;           // [16] warp partials
        if (rr < Rr) rs[j] = rel[rr * D + j];
        __syncthreads();
        if (rr < Rr) {
            const float* Wc = W1 + 256 * 128;
            float acc = 0.f;
            #pragma unroll 8
            for (int k = 0; k < 128; ++k)
                acc = fmaf(rs[k], Wc[k * 128 + j], acc);
            g_RelC[rr * D + j] = __float2half_rn(acc);
            float p = (acc + b1[j]) * w2[j];
            #pragma unroll
            for (int o = 16; o > 0; o >>= 1)
                p += __shfl_xor_sync(0xffffffffu, p, o);
            if ((j & 31) == 0) rp[grp * 4 + (j >> 5)] = p;
        }
        __syncthreads();
        if (j == 0 && rr < Rr)
            g_sr[rr] = rp[grp * 4] + rp[grp * 4 + 1] + rp[grp * 4 + 2] + rp[grp * 4 + 3];
        return;
    }

    // ======== GEMM blocks ========
    float* As  = smem;                        // [128][132]
    float* Bs  = smem + A_FLOATS;             // [128][264]
    float* w2d = smem + A_FLOATS + B_FLOATS;  // [256] = w2 | w2

    const int wid  = tid >> 5;
    const int lane = tid & 31;
    const int gid  = lane >> 2;
    const int tg   = lane & 3;
    const int warpM = wid & 3;
    const int warpN = wid >> 2;
    const int row0 = blockIdx.x * 128;

    if (tid < 256) w2d[tid] = w2[tid & 127];

    // fill A (tf32), zero-pad tail
    #pragma unroll
    for (int it = 0; it < 8; ++it) {
        int v = tid + it * 512;
        int r = v >> 5;
        int c = (v & 31) * 4;
        float4 val = make_float4(0.f, 0.f, 0.f, 0.f);
        int grow = row0 + r;
        if (grow < nrows) val = *(const float4*)&x[(size_t)grow * D + c];
        uint4 t;
        t.x = f2tf32(val.x); t.y = f2tf32(val.y); t.z = f2tf32(val.z); t.w = f2tf32(val.w);
        *(uint4*)&As[r * AS_STRIDE + c] = t;
    }
    // fill B: B[k][n] = W1[k][n] (n<128) else W1[128+k][n-128]
    #pragma unroll
    for (int it = 0; it < 16; ++it) {
        int v = tid + it * 512;
        int k = v >> 6;
        int n4 = (v & 63) * 4;
        const float* src = (n4 < 128) ? &W1[k * 128 + n4]
                                      : &W1[(128 + k) * 128 + (n4 - 128)];
        float4 val = *(const float4*)src;
        uint4 t;
        t.x = f2tf32(val.x); t.y = f2tf32(val.y); t.z = f2tf32(val.z); t.w = f2tf32(val.w);
        *(uint4*)&Bs[k * BS_STRIDE + n4] = t;
    }
    __syncthreads();

    float acc[2][8][4];
    #pragma unroll
    for (int mt = 0; mt < 2; ++mt)
        #pragma unroll
        for (int nt = 0; nt < 8; ++nt)
            #pragma unroll
            for (int q = 0; q < 4; ++q) acc[mt][nt][q] = 0.f;

    const int rbase = warpM * 32;
    const int cbase = warpN * 64;

    #pragma unroll 4
    for (int ks = 0; ks < 16; ++ks) {
        int k0 = ks * 8;
        uint32_t a[2][4];
        #pragma unroll
        for (int mt = 0; mt < 2; ++mt) {
            int r = rbase + mt * 16 + gid;
            a[mt][0] = *(uint32_t*)&As[r * AS_STRIDE + k0 + tg];
            a[mt][1] = *(uint32_t*)&As[(r + 8) * AS_STRIDE + k0 + tg];
            a[mt][2] = *(uint32_t*)&As[r * AS_STRIDE + k0 + tg + 4];
            a[mt][3] = *(uint32_t*)&As[(r + 8) * AS_STRIDE + k0 + tg + 4];
        }
        #pragma unroll
        for (int nt = 0; nt < 8; ++nt) {
            int cn = cbase + nt * 8 + gid;
            uint32_t b0 = *(uint32_t*)&Bs[(k0 + tg) * BS_STRIDE + cn];
            uint32_t b1v = *(uint32_t*)&Bs[(k0 + tg + 4) * BS_STRIDE + cn];
            #pragma unroll
            for (int mt = 0; mt < 2; ++mt) {
                asm volatile(
                    "mma.sync.aligned.m16n8k8.row.col.f32.tf32.tf32.f32 "
                    "{%0,%1,%2,%3}, {%4,%5,%6,%7}, {%8,%9}, {%0,%1,%2,%3};"
                    : "+f"(acc[mt][nt][0]), "+f"(acc[mt][nt][1]),
                      "+f"(acc[mt][nt][2]), "+f"(acc[mt][nt][3])
                    : "r"(a[mt][0]), "r"(a[mt][1]), "r"(a[mt][2]), "r"(a[mt][3]),
                      "r"(b0), "r"(b1v));
            }
        }
    }
    __syncthreads();   // done with As/Bs; red aliases As

    float* red = As;   // [2 sel][2 half][128 rows]

    // store Xa (fp16) / Xb (fp32) + per-row w2 partial dots (fp32)
    #pragma unroll
    for (int mt = 0; mt < 2; ++mt) {
        #pragma unroll
        for (int half = 0; half < 2; ++half) {
            int rloc = rbase + mt * 16 + half * 8 + gid;
            int row = row0 + rloc;
            bool valid = row < nrows;
            float p = 0.f;
            #pragma unroll
            for (int nt = 0; nt < 8; ++nt) {
                int col = cbase + nt * 8 + tg * 2;
                float c0 = acc[mt][nt][half * 2 + 0];
                float c1 = acc[mt][nt][half * 2 + 1];
                p = fmaf(c0, w2d[col], p);
                p = fmaf(c1, w2d[col + 1], p);
                if (valid) {
                    if (col < 128)
                        *(__half2*)&g_Xa[(size_t)row * D + col] =
                            __floats2half2_rn(c0, c1);
                    else
                        *(float2*)&g_Xb[(size_t)row * D + col - 128] =
                            make_float2(c0, c1);
                }
            }
            p += __shfl_xor_sync(0xffffffffu, p, 1);
            p += __shfl_xor_sync(0xffffffffu, p, 2);
            if (tg == 0)
                red[(warpN >> 1) * 256 + (warpN & 1) * 128 + rloc] = p;
        }
    }
    __syncthreads();
    if (tid < 128) {
        int row = row0 + tid;
        if (row < nrows) {
            g_sa[row] = red[tid] + red[128 + tid];
            g_sb[row] = red[256 + tid] + red[384 + tid];
        }
    }
}

// ---------------- gather: warp per dst node, TWO passes ----------------
// Pass 1: lane-parallel logits (32 independent scalar-load chains) -> smem.
// Pass 2: warp-synchronous vector accumulation from smem-cached records.
__global__ void __launch_bounds__(256)
gather_kernel(const float* __restrict__ b1, float* __restrict__ out, int Nn)
{
    __shared__ float    exs[8][CAP];
    __shared__ unsigned rcs[8][CAP];
    int warp = (blockIdx.x * blockDim.x + threadIdx.x) >> 5;
    int lane = threadIdx.x & 31;
    int wl = threadIdx.x >> 5;
    if (warp >= Nn) return;

    int degn = min(g_deg[warp], CAP);
    if (lane == 0) g_deg[warp] = 0;       // self-reset for next graph replay
    const unsigned* base = &g_packed[warp * CAP];

    // pass 1: logits -> exp; cache records; warp-reduce denom
    float denom = 0.f;
    float sbn = g_sb[warp];
    for (int j0 = 0; j0 < degn; j0 += 32) {
        int j = j0 + lane;
        float ex = 0.f;
        if (j < degn) {
            unsigned rec = base[j];
            rcs[wl][j] = rec;
            int s = rec & 0xFFFF;
            int t = rec >> 16;
            float b = g_sa[s] + sbn + g_sr[t];
            b = b > 0.f ? b : SLOPE * b;
            ex = __expf(b);
            exs[wl][j] = ex;
        }
        denom += ex;
    }
    #pragma unroll
    for (int o = 16; o > 0; o >>= 1)
        denom += __shfl_xor_sync(0xffffffffu, denom, o);
    __syncwarp();
    float inv = (degn > 0) ? 1.f / denom : 0.f;

    // pass 2: weighted accumulation of fp16 Xa[src] + fp16 RelC[et]
    float4 acc = make_float4(0.f, 0.f, 0.f, 0.f);
    #pragma unroll 4
    for (int j = 0; j < degn; ++j) {
        unsigned rec = rcs[wl][j];
        float alpha = exs[wl][j] * inv;
        int s = rec & 0xFFFF;
        int t = rec >> 16;
        uint2 xa2 = *(const uint2*)&g_Xa[(size_t)s * D + lane * 4];
        uint2 rc2 = *(const uint2*)&g_RelC[t * D + lane * 4];
        float2 f0 = __half22float2(*(__half2*)&xa2.x);
        float2 f1 = __half22float2(*(__half2*)&xa2.y);
        float2 r0 = __half22float2(*(__half2*)&rc2.x);
        float2 r1 = __half22float2(*(__half2*)&rc2.y);
        acc.x = fmaf(alpha, f0.x + r0.x, acc.x);
        acc.y = fmaf(alpha, f0.y + r0.y, acc.y);
        acc.z = fmaf(alpha, f1.x + r1.x, acc.z);
        acc.w = fmaf(alpha, f1.y + r1.y, acc.w);
    }

    float4 o = make_float4(0.f, 0.f, 0.f, 0.f);
    if (degn > 0) {
        float4 xb = *(const float4*)&g_Xb[(size_t)warp * D + lane * 4];
        float4 bb = *(const float4*)&b1[lane * 4];
        float vx = acc.x + xb.x + bb.x;
        float vy = acc.y + xb.y + bb.y;
        float vz = acc.z + xb.z + bb.z;
        float vw = acc.w + xb.w + bb.w;
        o.x = vx > 0.f ? vx : SLOPE * vx;
        o.y = vy > 0.f ? vy : SLOPE * vy;
        o.z = vz > 0.f ? vz : SLOPE * vz;
        o.w = vw > 0.f ? vw : SLOPE * vw;
    }
    *(float4*)&out[(size_t)warp * D + lane * 4] = o;
}

// ---------------- launch ----------------
extern "C" void kernel_launch(void* const* d_in, const int* in_sizes, int n_in,
                              void* d_out, int out_size)
{
    const float* x   = (const float*)d_in[0];
    const float* rel = (const float*)d_in[1];
    const float* W1  = (const float*)d_in[2];
    const float* b1  = (const float*)d_in[3];
    const float* w2  = (const float*)d_in[4];
    const int*   ei  = (const int*)d_in[5];
    const int*   et  = (const int*)d_in[6];
    int Nn = in_sizes[0] / D;
    int Rr = in_sizes[1] / D;
    int Ee = in_sizes[5] / 2;
    float* out = (float*)d_out;

    int gb = (Nn + 127) / 128;
    int grid = gb + (Rr + 3) / 4;

    cudaFuncSetAttribute(gemm_tc, cudaFuncAttributeMaxDynamicSharedMemorySize, SMEM_TOTAL);

    gemm_tc<<<grid, 512, SMEM_TOTAL>>>(x, rel, W1, b1, w2, ei, et, Nn, Rr, Ee, gb);
    gather_kernel<<<(Nn * 32 + 255) / 256, 256>>>(b1, out, Nn);
}

// round 9
// speedup vs baseline: 1.7548x; 1.6751x over previous
#include <cuda_runtime.h>
#include <cuda_fp16.h>
#include <cuda_bf16.h>
#include <cstdint>

#define NN 50000
#define EE 500000
#define RR 200
#define D 128
#define CAP 64
#define SLOPE 0.01f

// ---------------- scratch (static device globals; no allocation) ----------------
__device__ __half g_Xa[NN * D];       // x @ W1[0:128], fp16
__device__ float  g_Xb[NN * D];       // x @ W1[128:256], fp32
__device__ __half g_RelC[RR * D];     // rel @ W1[256:384], fp16
__device__ float  g_sa[NN];           // Xa . w2 (fp32 accum)
__device__ float  g_sb[NN];           // Xb . w2
__device__ float  g_sr[RR];           // (RelC + b1) . w2
__device__ int      g_deg[NN];        // in-degree per dst (zeroed via memset node)
__device__ unsigned g_packed[NN * CAP]; // src | (et<<16) per incoming edge

__device__ __forceinline__ uint32_t f2tf32(float v) {
    uint32_t o;
    asm("cvt.rna.tf32.f32 %0, %1;" : "=r"(o) : "f"(v));
    return o;
}

// ---------------- fused: edge fill + tf32 mma GEMM + relc ----------------
// Blocks [0, gb): GEMM (128 rows x 256 cols tile, K=128 resident)
// Blocks [gb, gb+ceil(R/4)): relation projection (4 relations/block)
// ALL blocks: grid-stride edge-fill prologue (latency hidden by A/B loads).
#define AS_STRIDE 132
#define BS_STRIDE 264
#define A_FLOATS (128 * AS_STRIDE)
#define B_FLOATS (128 * BS_STRIDE)
#define SMEM_TOTAL ((A_FLOATS + B_FLOATS + 256) * 4)

__global__ void __launch_bounds__(512, 1)
gemm_tc(const float* __restrict__ x, const float* __restrict__ rel,
        const float* __restrict__ W1, const float* __restrict__ b1,
        const float* __restrict__ w2,
        const int* __restrict__ ei, const int* __restrict__ et,
        int nrows, int Rr, int Ee, int gb)
{
    extern __shared__ float smem[];
    const int tid = threadIdx.x;          // 512

    // ======== edge-fill prologue (all blocks) ========
    {
        int stride = gridDim.x * 512;
        for (int e = blockIdx.x * 512 + tid; e < Ee; e += stride) {
            int d = ei[Ee + e];
            int pos = atomicAdd(&g_deg[d], 1);
            if (pos < CAP)
                g_packed[d * CAP + pos] = (unsigned)ei[e] | ((unsigned)et[e] << 16);
        }
    }

    // ======== relation blocks ========
    if (blockIdx.x >= gb) {
        int rb = blockIdx.x - gb;
        int grp = tid >> 7;               // 0..3
        int j = tid & 127;
        int rr = rb * 4 + grp;
        float* rs = smem + grp * 128;     // [4][128]
        float* rp = smem + 512;           // [16] warp partials
        if (rr < Rr) rs[j] = rel[rr * D + j];
        __syncthreads();
        if (rr < Rr) {
            const float* Wc = W1 + 256 * 128;
            float acc = 0.f;
            #pragma unroll 8
            for (int k = 0; k < 128; ++k)
                acc = fmaf(rs[k], Wc[k * 128 + j], acc);
            g_RelC[rr * D + j] = __float2half_rn(acc);
            float p = (acc + b1[j]) * w2[j];
            #pragma unroll
            for (int o = 16; o > 0; o >>= 1)
                p += __shfl_xor_sync(0xffffffffu, p, o);
            if ((j & 31) == 0) rp[grp * 4 + (j >> 5)] = p;
        }
        __syncthreads();
        if (j == 0 && rr < Rr)
            g_sr[rr] = rp[grp * 4] + rp[grp * 4 + 1] + rp[grp * 4 + 2] + rp[grp * 4 + 3];
        return;
    }

    // ======== GEMM blocks ========
    float* As  = smem;                        // [128][132]
    float* Bs  = smem + A_FLOATS;             // [128][264]
    float* w2d = smem + A_FLOATS + B_FLOATS;  // [256] = w2 | w2

    const int wid  = tid >> 5;
    const int lane = tid & 31;
    const int gid  = lane >> 2;
    const int tg   = lane & 3;
    const int warpM = wid & 3;
    const int warpN = wid >> 2;
    const int row0 = blockIdx.x * 128;

    if (tid < 256) w2d[tid] = w2[tid & 127];

    // fill A (tf32), zero-pad tail
    #pragma unroll
    for (int it = 0; it < 8; ++it) {
        int v = tid + it * 512;
        int r = v >> 5;
        int c = (v & 31) * 4;
        float4 val = make_float4(0.f, 0.f, 0.f, 0.f);
        int grow = row0 + r;
        if (grow < nrows) val = *(const float4*)&x[(size_t)grow * D + c];
        uint4 t;
        t.x = f2tf32(val.x); t.y = f2tf32(val.y); t.z = f2tf32(val.z); t.w = f2tf32(val.w);
        *(uint4*)&As[r * AS_STRIDE + c] = t;
    }
    // fill B: B[k][n] = W1[k][n] (n<128) else W1[128+k][n-128]
    #pragma unroll
    for (int it = 0; it < 16; ++it) {
        int v = tid + it * 512;
        int k = v >> 6;
        int n4 = (v & 63) * 4;
        const float* src = (n4 < 128) ? &W1[k * 128 + n4]
                                      : &W1[(128 + k) * 128 + (n4 - 128)];
        float4 val = *(const float4*)src;
        uint4 t;
        t.x = f2tf32(val.x); t.y = f2tf32(val.y); t.z = f2tf32(val.z); t.w = f2tf32(val.w);
        *(uint4*)&Bs[k * BS_STRIDE + n4] = t;
    }
    __syncthreads();

    float acc[2][8][4];
    #pragma unroll
    for (int mt = 0; mt < 2; ++mt)
        #pragma unroll
        for (int nt = 0; nt < 8; ++nt)
            #pragma unroll
            for (int q = 0; q < 4; ++q) acc[mt][nt][q] = 0.f;

    const int rbase = warpM * 32;
    const int cbase = warpN * 64;

    #pragma unroll 4
    for (int ks = 0; ks < 16; ++ks) {
        int k0 = ks * 8;
        uint32_t a[2][4];
        #pragma unroll
        for (int mt = 0; mt < 2; ++mt) {
            int r = rbase + mt * 16 + gid;
            a[mt][0] = *(uint32_t*)&As[r * AS_STRIDE + k0 + tg];
            a[mt][1] = *(uint32_t*)&As[(r + 8) * AS_STRIDE + k0 + tg];
            a[mt][2] = *(uint32_t*)&As[r * AS_STRIDE + k0 + tg + 4];
            a[mt][3] = *(uint32_t*)&As[(r + 8) * AS_STRIDE + k0 + tg + 4];
        }
        #pragma unroll
        for (int nt = 0; nt < 8; ++nt) {
            int cn = cbase + nt * 8 + gid;
            uint32_t b0 = *(uint32_t*)&Bs[(k0 + tg) * BS_STRIDE + cn];
            uint32_t b1v = *(uint32_t*)&Bs[(k0 + tg + 4) * BS_STRIDE + cn];
            #pragma unroll
            for (int mt = 0; mt < 2; ++mt) {
                asm volatile(
                    "mma.sync.aligned.m16n8k8.row.col.f32.tf32.tf32.f32 "
                    "{%0,%1,%2,%3}, {%4,%5,%6,%7}, {%8,%9}, {%0,%1,%2,%3};"
                    : "+f"(acc[mt][nt][0]), "+f"(acc[mt][nt][1]),
                      "+f"(acc[mt][nt][2]), "+f"(acc[mt][nt][3])
                    : "r"(a[mt][0]), "r"(a[mt][1]), "r"(a[mt][2]), "r"(a[mt][3]),
                      "r"(b0), "r"(b1v));
            }
        }
    }
    __syncthreads();   // done with As/Bs; red aliases As

    float* red = As;   // [2 sel][2 half][128 rows]

    // store Xa (fp16) / Xb (fp32) + per-row w2 partial dots (fp32)
    #pragma unroll
    for (int mt = 0; mt < 2; ++mt) {
        #pragma unroll
        for (int half = 0; half < 2; ++half) {
            int rloc = rbase + mt * 16 + half * 8 + gid;
            int row = row0 + rloc;
            bool valid = row < nrows;
            float p = 0.f;
            #pragma unroll
            for (int nt = 0; nt < 8; ++nt) {
                int col = cbase + nt * 8 + tg * 2;
                float c0 = acc[mt][nt][half * 2 + 0];
                float c1 = acc[mt][nt][half * 2 + 1];
                p = fmaf(c0, w2d[col], p);
                p = fmaf(c1, w2d[col + 1], p);
                if (valid) {
                    if (col < 128)
                        *(__half2*)&g_Xa[(size_t)row * D + col] =
                            __floats2half2_rn(c0, c1);
                    else
                        *(float2*)&g_Xb[(size_t)row * D + col - 128] =
                            make_float2(c0, c1);
                }
            }
            p += __shfl_xor_sync(0xffffffffu, p, 1);
            p += __shfl_xor_sync(0xffffffffu, p, 2);
            if (tg == 0)
                red[(warpN >> 1) * 256 + (warpN & 1) * 128 + rloc] = p;
        }
    }
    __syncthreads();
    if (tid < 128) {
        int row = row0 + tid;
        if (row < nrows) {
            g_sa[row] = red[tid] + red[128 + tid];
            g_sb[row] = red[256 + tid] + red[384 + tid];
        }
    }
}

// ---------------- gather: warp per dst node, TWO passes (R6-measured config) ----------------
__global__ void __launch_bounds__(256)
gather_kernel(const float* __restrict__ b1, float* __restrict__ out, int Nn)
{
    __shared__ float    exs[8][CAP];
    __shared__ unsigned rcs[8][CAP];
    int warp = (blockIdx.x * blockDim.x + threadIdx.x) >> 5;
    int lane = threadIdx.x & 31;
    int wl = threadIdx.x >> 5;
    if (warp >= Nn) return;

    int degn = min(g_deg[warp], CAP);
    const unsigned* base = &g_packed[warp * CAP];

    // pass 1: logits -> exp; cache records; warp-reduce denom
    float denom = 0.f;
    float sbn = g_sb[warp];
    for (int j0 = 0; j0 < degn; j0 += 32) {
        int j = j0 + lane;
        float ex = 0.f;
        if (j < degn) {
            unsigned rec = base[j];
            rcs[wl][j] = rec;
            int s = rec & 0xFFFF;
            int t = rec >> 16;
            float b = g_sa[s] + sbn + g_sr[t];
            b = b > 0.f ? b : SLOPE * b;
            ex = __expf(b);
            exs[wl][j] = ex;
        }
        denom += ex;
    }
    #pragma unroll
    for (int o = 16; o > 0; o >>= 1)
        denom += __shfl_xor_sync(0xffffffffu, denom, o);
    __syncwarp();
    float inv = (degn > 0) ? 1.f / denom : 0.f;

    // pass 2: weighted accumulation of fp16 Xa[src] + fp16 RelC[et]
    float4 acc = make_float4(0.f, 0.f, 0.f, 0.f);
    #pragma unroll 2
    for (int j = 0; j < degn; ++j) {
        unsigned rec = rcs[wl][j];
        float alpha = exs[wl][j] * inv;
        int s = rec & 0xFFFF;
        int t = rec >> 16;
        uint2 xa2 = *(const uint2*)&g_Xa[(size_t)s * D + lane * 4];
        uint2 rc2 = *(const uint2*)&g_RelC[t * D + lane * 4];
        float2 f0 = __half22float2(*(__half2*)&xa2.x);
        float2 f1 = __half22float2(*(__half2*)&xa2.y);
        float2 r0 = __half22float2(*(__half2*)&rc2.x);
        float2 r1 = __half22float2(*(__half2*)&rc2.y);
        acc.x = fmaf(alpha, f0.x + r0.x, acc.x);
        acc.y = fmaf(alpha, f0.y + r0.y, acc.y);
        acc.z = fmaf(alpha, f1.x + r1.x, acc.z);
        acc.w = fmaf(alpha, f1.y + r1.y, acc.w);
    }

    float4 o = make_float4(0.f, 0.f, 0.f, 0.f);
    if (degn > 0) {
        float4 xb = *(const float4*)&g_Xb[(size_t)warp * D + lane * 4];
        float4 bb = *(const float4*)&b1[lane * 4];
        float vx = acc.x + xb.x + bb.x;
        float vy = acc.y + xb.y + bb.y;
        float vz = acc.z + xb.z + bb.z;
        float vw = acc.w + xb.w + bb.w;
        o.x = vx > 0.f ? vx : SLOPE * vx;
        o.y = vy > 0.f ? vy : SLOPE * vy;
        o.z = vz > 0.f ? vz : SLOPE * vz;
        o.w = vw > 0.f ? vw : SLOPE * vw;
    }
    *(float4*)&out[(size_t)warp * D + lane * 4] = o;
}

// ---------------- launch ----------------
extern "C" void kernel_launch(void* const* d_in, const int* in_sizes, int n_in,
                              void* d_out, int out_size)
{
    const float* x   = (const float*)d_in[0];
    const float* rel = (const float*)d_in[1];
    const float* W1  = (const float*)d_in[2];
    const float* b1  = (const float*)d_in[3];
    const float* w2  = (const float*)d_in[4];
    const int*   ei  = (const int*)d_in[5];
    const int*   et  = (const int*)d_in[6];
    int Nn = in_sizes[0] / D;
    int Rr = in_sizes[1] / D;
    int Ee = in_sizes[5] / 2;
    float* out = (float*)d_out;

    int gb = (Nn + 127) / 128;
    int grid = gb + (Rr + 3) / 4;

    // zero g_deg via memset node (no kernel launch, no allocation)
    void* degp = nullptr;
    cudaGetSymbolAddress(&degp, g_deg);
    cudaMemsetAsync(degp, 0, (size_t)Nn * sizeof(int));

    cudaFuncSetAttribute(gemm_tc, cudaFuncAttributeMaxDynamicSharedMemorySize, SMEM_TOTAL);

    gemm_tc<<<grid, 512, SMEM_TOTAL>>>(x, rel, W1, b1, w2, ei, et, Nn, Rr, Ee, gb);
    gather_kernel<<<(Nn * 32 + 255) / 256, 256>>>(b1, out, Nn);
}

// round 10
// speedup vs baseline: 1.9914x; 1.1348x over previous
#include <cuda_runtime.h>
#include <cuda_fp16.h>
#include <cuda_bf16.h>
#include <cstdint>

#define NN 50000
#define EE 500000
#define RR 200
#define D 128
#define CAP 64
#define SLOPE 0.01f

// ---------------- scratch (static device globals; no allocation) ----------------
__device__ __half g_Xa[NN * D];       // x @ W1[0:128], fp16
__device__ float  g_Xb[NN * D];       // x @ W1[128:256], fp32
__device__ __half g_RelC[RR * D];     // rel @ W1[256:384], fp16
__device__ float  g_sa[NN];           // Xa . w2 (fp32 accum)
__device__ float  g_sb[NN];           // Xb . w2
__device__ float  g_sr[RR];           // (RelC + b1) . w2
__device__ int      g_deg[NN];        // in-degree per dst (zeroed via memset node)
__device__ unsigned g_packed[NN * CAP]; // src | (et<<16) per incoming edge

__device__ __forceinline__ uint32_t smem_u32(const void* p) {
    uint32_t a;
    asm("{ .reg .u64 t; cvta.to.shared.u64 t, %1; cvt.u32.u64 %0, t; }" : "=r"(a) : "l"(p));
    return a;
}

#define LDM_X4(R, addr) \
    asm volatile("ldmatrix.sync.aligned.m8n8.x4.shared.b16 {%0,%1,%2,%3}, [%4];" \
        : "=r"((R)[0]), "=r"((R)[1]), "=r"((R)[2]), "=r"((R)[3]) : "r"(addr))
#define LDM_X2T(R, addr) \
    asm volatile("ldmatrix.sync.aligned.m8n8.x2.trans.shared.b16 {%0,%1}, [%2];" \
        : "=r"((R)[0]), "=r"((R)[1]) : "r"(addr))
#define MMA16(C, A, B) \
    asm volatile("mma.sync.aligned.m16n8k16.row.col.f32.f16.f16.f32 " \
        "{%0,%1,%2,%3}, {%4,%5,%6,%7}, {%8,%9}, {%0,%1,%2,%3};" \
        : "+f"((C)[0]), "+f"((C)[1]), "+f"((C)[2]), "+f"((C)[3]) \
        : "r"((A)[0]), "r"((A)[1]), "r"((A)[2]), "r"((A)[3]), "r"((B)[0]), "r"((B)[1]))

// ---------------- smem layout ----------------
// mainloop: A halves [128][ASH] at 0, B halves [128 k][BSH n] at A_BYTES (ends 102400)
// epilogue staging (after sync, overlaps A/B): XbS f32 [128][144] at 0, XaS half [128][160] at XBS_BYTES
// persistent: w2d (256 f32) at W2D_OFF, red (512 f32) at RED_OFF
#define ASH 136
#define BSH 264
#define A_BYTES (128 * ASH * 2)          // 34816; 272B stride ≡16 (mod 128) -> ldmatrix conflict-free
#define B_BYTES (128 * BSH * 2)          // 67584; 528B stride ≡16 (mod 128)
#define XBS_STRIDE 144                   // ≡16 (mod 32) words -> conflict-free uint4 readback
#define XAS_STRIDE 160                   // 320B ≡16 words (mod 32)
#define XBS_BYTES (128 * XBS_STRIDE * 4) // 73728
#define XAS_BYTES (128 * XAS_STRIDE * 2) // 40960
#define W2D_OFF (XBS_BYTES + XAS_BYTES)  // 114688
#define RED_OFF (W2D_OFF + 256 * 4)
#define SMEM_TOTAL (RED_OFF + 512 * 4)   // 117760 B

// ---------------- fused: edge fill + fp16 mma GEMM + relc ----------------
__global__ void __launch_bounds__(512, 1)
gemm_tc(const float* __restrict__ x, const float* __restrict__ rel,
        const float* __restrict__ W1, const float* __restrict__ b1,
        const float* __restrict__ w2,
        const int* __restrict__ ei, const int* __restrict__ et,
        int nrows, int Rr, int Ee, int gb)
{
    extern __shared__ float smem[];
    char* smemc = (char*)smem;
    const int tid = threadIdx.x;          // 512

    // ======== edge-fill prologue (all blocks) ========
    {
        int stride = gridDim.x * 512;
        for (int e = blockIdx.x * 512 + tid; e < Ee; e += stride) {
            int d = ei[Ee + e];
            int pos = atomicAdd(&g_deg[d], 1);
            if (pos < CAP)
                g_packed[d * CAP + pos] = (unsigned)ei[e] | ((unsigned)et[e] << 16);
        }
    }

    // ======== relation blocks ========
    if (blockIdx.x >= gb) {
        int rb = blockIdx.x - gb;
        int grp = tid >> 7;               // 0..3
        int j = tid & 127;
        int rr = rb * 4 + grp;
        float* rs = smem + grp * 128;     // [4][128]
        float* rp = smem + 512;           // [16] warp partials
        if (rr < Rr) rs[j] = rel[rr * D + j];
        __syncthreads();
        if (rr < Rr) {
            const float* Wc = W1 + 256 * 128;
            float acc = 0.f;
            #pragma unroll 8
            for (int k = 0; k < 128; ++k)
                acc = fmaf(rs[k], Wc[k * 128 + j], acc);
            g_RelC[rr * D + j] = __float2half_rn(acc);
            float p = (acc + b1[j]) * w2[j];
            #pragma unroll
            for (int o = 16; o > 0; o >>= 1)
                p += __shfl_xor_sync(0xffffffffu, p, o);
            if ((j & 31) == 0) rp[grp * 4 + (j >> 5)] = p;
        }
        __syncthreads();
        if (j == 0 && rr < Rr)
            g_sr[rr] = rp[grp * 4] + rp[grp * 4 + 1] + rp[grp * 4 + 2] + rp[grp * 4 + 3];
        return;
    }

    // ======== GEMM blocks ========
    __half* Asm = (__half*)smemc;
    __half* Bsm = (__half*)(smemc + A_BYTES);
    float*  w2d = (float*)(smemc + W2D_OFF);

    const int wid  = tid >> 5;
    const int lane = tid & 31;
    const int gid  = lane >> 2;
    const int tg   = lane & 3;
    const int warpM = wid & 3;
    const int warpN = wid >> 2;
    const int row0 = blockIdx.x * 128;

    if (tid < 256) w2d[tid] = w2[tid & 127];

    // fill A (fp16 halves), zero-pad tail rows
    #pragma unroll
    for (int it = 0; it < 8; ++it) {
        int v = tid + it * 512;           // float4 id, 4096 total
        int r = v >> 5;
        int c = (v & 31) * 4;
        float4 val = make_float4(0.f, 0.f, 0.f, 0.f);
        int grow = row0 + r;
        if (grow < nrows) val = *(const float4*)&x[(size_t)grow * D + c];
        __half2 h01 = __floats2half2_rn(val.x, val.y);
        __half2 h23 = __floats2half2_rn(val.z, val.w);
        uint2 u = make_uint2(*(uint32_t*)&h01, *(uint32_t*)&h23);
        *(uint2*)&Asm[r * ASH + c] = u;
    }
    // fill B halves [k][n]: B[k][n] = W1[k][n] (n<128) else W1[128+k][n-128]
    #pragma unroll
    for (int it = 0; it < 16; ++it) {
        int v = tid + it * 512;           // float4 id, 8192 total
        int k = v >> 6;
        int n4 = (v & 63) * 4;
        const float* src = (n4 < 128) ? &W1[k * 128 + n4]
                                      : &W1[(128 + k) * 128 + (n4 - 128)];
        float4 val = *(const float4*)src;
        __half2 h01 = __floats2half2_rn(val.x, val.y);
        __half2 h23 = __floats2half2_rn(val.z, val.w);
        uint2 u = make_uint2(*(uint32_t*)&h01, *(uint32_t*)&h23);
        *(uint2*)&Bsm[k * BSH + n4] = u;
    }
    __syncthreads();

    float acc[2][8][4];
    #pragma unroll
    for (int mt = 0; mt < 2; ++mt)
        #pragma unroll
        for (int nt = 0; nt < 8; ++nt)
            #pragma unroll
            for (int q = 0; q < 4; ++q) acc[mt][nt][q] = 0.f;

    const int rbase = warpM * 32;
    const int cbase = warpN * 64;

    // ldmatrix lane address bases (bytes, shared space)
    const uint32_t sb = smem_u32(smemc);
    uint32_t aB0 = sb + (uint32_t)(((rbase + (lane & 7) + ((lane >> 3) & 1) * 8) * ASH
                                    + ((lane >> 4) * 8)) * 2);
    uint32_t aB1 = aB0 + 16 * ASH * 2;
    uint32_t bB  = sb + A_BYTES + (uint32_t)((((lane & 15)) * BSH + cbase) * 2);

    #pragma unroll
    for (int ks = 0; ks < 8; ++ks) {      // K=128, 16 per step
        uint32_t a0[4], a1[4];
        LDM_X4(a0, aB0);
        LDM_X4(a1, aB1);
        #pragma unroll
        for (int nt = 0; nt < 8; ++nt) {
            uint32_t b[2];
            LDM_X2T(b, bB + nt * 16);     // nt*8 halves
            MMA16(acc[0][nt], a0, b);
            MMA16(acc[1][nt], a1, b);
        }
        aB0 += 32;                        // k += 16 halves
        aB1 += 32;
        bB  += 16 * BSH * 2;
    }
    __syncthreads();   // done with Asm/Bsm; staging overlays them

    float*  XbS = (float*)smemc;                    // [128][144]
    __half* XaS = (__half*)(smemc + XBS_BYTES);     // [128][160]
    float*  red = (float*)(smemc + RED_OFF);        // [2 sel][2 half][128]

    // frags -> staging + per-row w2 partial dots
    #pragma unroll
    for (int mt = 0; mt < 2; ++mt) {
        #pragma unroll
        for (int half = 0; half < 2; ++half) {
            int rloc = rbase + mt * 16 + half * 8 + gid;
            float p = 0.f;
            #pragma unroll
            for (int nt = 0; nt < 8; ++nt) {
                int col = cbase + nt * 8 + tg * 2;
                float c0 = acc[mt][nt][half * 2 + 0];
                float c1 = acc[mt][nt][half * 2 + 1];
                p = fmaf(c0, w2d[col], p);
                p = fmaf(c1, w2d[col + 1], p);
                if (col < 128)
                    *(__half2*)&XaS[rloc * XAS_STRIDE + col] = __floats2half2_rn(c0, c1);
                else
                    *(float2*)&XbS[rloc * XBS_STRIDE + (col - 128)] = make_float2(c0, c1);
            }
            p += __shfl_xor_sync(0xffffffffu, p, 1);
            p += __shfl_xor_sync(0xffffffffu, p, 2);
            if (tg == 0)
                red[(warpN >> 1) * 256 + (warpN & 1) * 128 + rloc] = p;
        }
    }
    __syncthreads();

    // coalesced write-out: thread = row*4 + part
    {
        int r = tid >> 2;
        int part = tid & 3;
        int row = row0 + r;
        if (row < nrows) {
            const uint4* sa4 = (const uint4*)((char*)XaS + (size_t)r * XAS_STRIDE * 2);
            uint4* da4 = (uint4*)&g_Xa[(size_t)row * D];
            #pragma unroll
            for (int i = 0; i < 4; ++i) {
                int c = i * 4 + part;     // 16 chunks of 16B per Xa row
                da4[c] = sa4[c];
            }
            const uint4* sb4 = (const uint4*)((char*)XbS + (size_t)r * XBS_STRIDE * 4);
            uint4* db4 = (uint4*)&g_Xb[(size_t)row * D];
            #pragma unroll
            for (int i = 0; i < 8; ++i) {
                int c = i * 4 + part;     // 32 chunks of 16B per Xb row
                db4[c] = sb4[c];
            }
        }
        if (tid < 128) {
            int row2 = row0 + tid;
            if (row2 < nrows) {
                g_sa[row2] = red[tid] + red[128 + tid];
                g_sb[row2] = red[256 + tid] + red[384 + tid];
            }
        }
    }
}

// ---------------- gather: warp per dst node, TWO passes (R9-measured config) ----------------
__global__ void __launch_bounds__(256)
gather_kernel(const float* __restrict__ b1, float* __restrict__ out, int Nn)
{
    __shared__ float    exs[8][CAP];
    __shared__ unsigned rcs[8][CAP];
    int warp = (blockIdx.x * blockDim.x + threadIdx.x) >> 5;
    int lane = threadIdx.x & 31;
    int wl = threadIdx.x >> 5;
    if (warp >= Nn) return;

    int degn = min(g_deg[warp], CAP);
    const unsigned* base = &g_packed[warp * CAP];

    // pass 1: logits -> exp; cache records; warp-reduce denom
    float denom = 0.f;
    float sbn = g_sb[warp];
    for (int j0 = 0; j0 < degn; j0 += 32) {
        int j = j0 + lane;
        float ex = 0.f;
        if (j < degn) {
            unsigned rec = base[j];
            rcs[wl][j] = rec;
            int s = rec & 0xFFFF;
            int t = rec >> 16;
            float b = g_sa[s] + sbn + g_sr[t];
            b = b > 0.f ? b : SLOPE * b;
            ex = __expf(b);
            exs[wl][j] = ex;
        }
        denom += ex;
    }
    #pragma unroll
    for (int o = 16; o > 0; o >>= 1)
        denom += __shfl_xor_sync(0xffffffffu, denom, o);
    __syncwarp();
    float inv = (degn > 0) ? 1.f / denom : 0.f;

    // pass 2: weighted accumulation of fp16 Xa[src] + fp16 RelC[et]
    float4 acc = make_float4(0.f, 0.f, 0.f, 0.f);
    #pragma unroll 2
    for (int j = 0; j < degn; ++j) {
        unsigned rec = rcs[wl][j];
        float alpha = exs[wl][j] * inv;
        int s = rec & 0xFFFF;
        int t = rec >> 16;
        uint2 xa2 = *(const uint2*)&g_Xa[(size_t)s * D + lane * 4];
        uint2 rc2 = *(const uint2*)&g_RelC[t * D + lane * 4];
        float2 f0 = __half22float2(*(__half2*)&xa2.x);
        float2 f1 = __half22float2(*(__half2*)&xa2.y);
        float2 r0 = __half22float2(*(__half2*)&rc2.x);
        float2 r1 = __half22float2(*(__half2*)&rc2.y);
        acc.x = fmaf(alpha, f0.x + r0.x, acc.x);
        acc.y = fmaf(alpha, f0.y + r0.y, acc.y);
        acc.z = fmaf(alpha, f1.x + r1.x, acc.z);
        acc.w = fmaf(alpha, f1.y + r1.y, acc.w);
    }

    float4 o = make_float4(0.f, 0.f, 0.f, 0.f);
    if (degn > 0) {
        float4 xb = *(const float4*)&g_Xb[(size_t)warp * D + lane * 4];
        float4 bb = *(const float4*)&b1[lane * 4];
        float vx = acc.x + xb.x + bb.x;
        float vy = acc.y + xb.y + bb.y;
        float vz = acc.z + xb.z + bb.z;
        float vw = acc.w + xb.w + bb.w;
        o.x = vx > 0.f ? vx : SLOPE * vx;
        o.y = vy > 0.f ? vy : SLOPE * vy;
        o.z = vz > 0.f ? vz : SLOPE * vz;
        o.w = vw > 0.f ? vw : SLOPE * vw;
    }
    *(float4*)&out[(size_t)warp * D + lane * 4] = o;
}

// ---------------- launch ----------------
extern "C" void kernel_launch(void* const* d_in, const int* in_sizes, int n_in,
                              void* d_out, int out_size)
{
    const float* x   = (const float*)d_in[0];
    const float* rel = (const float*)d_in[1];
    const float* W1  = (const float*)d_in[2];
    const float* b1  = (const float*)d_in[3];
    const float* w2  = (const float*)d_in[4];
    const int*   ei  = (const int*)d_in[5];
    const int*   et  = (const int*)d_in[6];
    int Nn = in_sizes[0] / D;
    int Rr = in_sizes[1] / D;
    int Ee = in_sizes[5] / 2;
    float* out = (float*)d_out;

    int gb = (Nn + 127) / 128;
    int grid = gb + (Rr + 3) / 4;

    void* degp = nullptr;
    cudaGetSymbolAddress(&degp, g_deg);
    cudaMemsetAsync(degp, 0, (size_t)Nn * sizeof(int));

    cudaFuncSetAttribute(gemm_tc, cudaFuncAttributeMaxDynamicSharedMemorySize, SMEM_TOTAL);

    gemm_tc<<<grid, 512, SMEM_TOTAL>>>(x, rel, W1, b1, w2, ei, et, Nn, Rr, Ee, gb);
    gather_kernel<<<(Nn * 32 + 255) / 256, 256>>>(b1, out, Nn);
}

// round 11
// speedup vs baseline: 2.1591x; 1.0842x over previous
#include <cuda_runtime.h>
#include <cuda_fp16.h>
#include <cuda_bf16.h>
#include <cstdint>

#define NN 50000
#define EE 500000
#define RR 200
#define D 128
#define CAP 64
#define SLOPE 0.01f

// ---------------- scratch (static device globals; no allocation) ----------------
__device__ __half g_Xa[NN * D];       // x @ W1[0:128], fp16
__device__ __half g_Xb[NN * D];       // x @ W1[128:256] + b1, fp16
__device__ __half g_RelC[RR * D];     // rel @ W1[256:384], fp16
__device__ float  g_sa[NN];           // Xa . w2 (fp32 accum)
__device__ float  g_sb[NN];           // Xb . w2 (raw, without b1)
__device__ float  g_sr[RR];           // (RelC + b1) . w2
__device__ int      g_deg[NN];        // in-degree per dst (zeroed via memset node)
__device__ unsigned g_packed[NN * CAP]; // src | (et<<16) per incoming edge

__device__ __forceinline__ uint32_t smem_u32(const void* p) {
    uint32_t a;
    asm("{ .reg .u64 t; cvta.to.shared.u64 t, %1; cvt.u32.u64 %0, t; }" : "=r"(a) : "l"(p));
    return a;
}

#define LDM_X4(R, addr) \
    asm volatile("ldmatrix.sync.aligned.m8n8.x4.shared.b16 {%0,%1,%2,%3}, [%4];" \
        : "=r"((R)[0]), "=r"((R)[1]), "=r"((R)[2]), "=r"((R)[3]) : "r"(addr))
#define LDM_X2T(R, addr) \
    asm volatile("ldmatrix.sync.aligned.m8n8.x2.trans.shared.b16 {%0,%1}, [%2];" \
        : "=r"((R)[0]), "=r"((R)[1]) : "r"(addr))
#define MMA16(C, A, B) \
    asm volatile("mma.sync.aligned.m16n8k16.row.col.f32.f16.f16.f32 " \
        "{%0,%1,%2,%3}, {%4,%5,%6,%7}, {%8,%9}, {%0,%1,%2,%3};" \
        : "+f"((C)[0]), "+f"((C)[1]), "+f"((C)[2]), "+f"((C)[3]) \
        : "r"((A)[0]), "r"((A)[1]), "r"((A)[2]), "r"((A)[3]), "r"((B)[0]), "r"((B)[1]))

// ---------------- smem layout ----------------
// mainloop: A halves [128][ASH] at 0, B halves [128 k][BSH n] at A_BYTES
// epilogue staging (overlays A/B after sync): XaS half [128][136] at 0,
//   XbS half [128][136] at XS_BYTES
// persistent (past mainloop end): w2d[256] f32, b1d[128] f32, red[512] f32
#define ASH 136
#define BSH 264
#define A_BYTES (128 * ASH * 2)          // 34816; 272B stride ≡16 (mod 128) -> ldmatrix conflict-free
#define B_BYTES (128 * BSH * 2)          // 67584
#define XS_STRIDE 136
#define XS_BYTES (128 * XS_STRIDE * 2)   // 34816
#define W2D_OFF (A_BYTES + B_BYTES)      // 102400
#define B1D_OFF (W2D_OFF + 256 * 4)      // 103424
#define RED_OFF (B1D_OFF + 128 * 4)      // 103936
#define SMEM_TOTAL (RED_OFF + 512 * 4)   // 105984 B

// ---------------- fused: edge fill + fp16 mma GEMM + relc ----------------
__global__ void __launch_bounds__(512, 1)
gemm_tc(const float* __restrict__ x, const float* __restrict__ rel,
        const float* __restrict__ W1, const float* __restrict__ b1,
        const float* __restrict__ w2,
        const int* __restrict__ ei, const int* __restrict__ et,
        int nrows, int Rr, int Ee, int gb)
{
    extern __shared__ float smem[];
    char* smemc = (char*)smem;
    const int tid = threadIdx.x;          // 512

    // ======== edge-fill prologue (all blocks) ========
    {
        int stride = gridDim.x * 512;
        for (int e = blockIdx.x * 512 + tid; e < Ee; e += stride) {
            int d = ei[Ee + e];
            int pos = atomicAdd(&g_deg[d], 1);
            if (pos < CAP)
                g_packed[d * CAP + pos] = (unsigned)ei[e] | ((unsigned)et[e] << 16);
        }
    }

    // ======== relation blocks ========
    if (blockIdx.x >= gb) {
        int rb = blockIdx.x - gb;
        int grp = tid >> 7;               // 0..3
        int j = tid & 127;
        int rr = rb * 4 + grp;
        float* rs = smem + grp * 128;     // [4][128]
        float* rp = smem + 512;           // [16] warp partials
        if (rr < Rr) rs[j] = rel[rr * D + j];
        __syncthreads();
        if (rr < Rr) {
            const float* Wc = W1 + 256 * 128;
            float acc = 0.f;
            #pragma unroll 8
            for (int k = 0; k < 128; ++k)
                acc = fmaf(rs[k], Wc[k * 128 + j], acc);
            g_RelC[rr * D + j] = __float2half_rn(acc);
            float p = (acc + b1[j]) * w2[j];
            #pragma unroll
            for (int o = 16; o > 0; o >>= 1)
                p += __shfl_xor_sync(0xffffffffu, p, o);
            if ((j & 31) == 0) rp[grp * 4 + (j >> 5)] = p;
        }
        __syncthreads();
        if (j == 0 && rr < Rr)
            g_sr[rr] = rp[grp * 4] + rp[grp * 4 + 1] + rp[grp * 4 + 2] + rp[grp * 4 + 3];
        return;
    }

    // ======== GEMM blocks ========
    __half* Asm = (__half*)smemc;
    __half* Bsm = (__half*)(smemc + A_BYTES);
    float*  w2d = (float*)(smemc + W2D_OFF);
    float*  b1d = (float*)(smemc + B1D_OFF);

    const int wid  = tid >> 5;
    const int lane = tid & 31;
    const int gid  = lane >> 2;
    const int tg   = lane & 3;
    const int warpM = wid & 3;
    const int warpN = wid >> 2;
    const int row0 = blockIdx.x * 128;

    if (tid < 256) w2d[tid] = w2[tid & 127];
    else if (tid < 384) b1d[tid - 256] = b1[tid - 256];

    // fill A (fp16 halves), zero-pad tail rows
    #pragma unroll
    for (int it = 0; it < 8; ++it) {
        int v = tid + it * 512;           // float4 id, 4096 total
        int r = v >> 5;
        int c = (v & 31) * 4;
        float4 val = make_float4(0.f, 0.f, 0.f, 0.f);
        int grow = row0 + r;
        if (grow < nrows) val = *(const float4*)&x[(size_t)grow * D + c];
        __half2 h01 = __floats2half2_rn(val.x, val.y);
        __half2 h23 = __floats2half2_rn(val.z, val.w);
        uint2 u = make_uint2(*(uint32_t*)&h01, *(uint32_t*)&h23);
        *(uint2*)&Asm[r * ASH + c] = u;
    }
    // fill B halves [k][n]: B[k][n] = W1[k][n] (n<128) else W1[128+k][n-128]
    #pragma unroll
    for (int it = 0; it < 16; ++it) {
        int v = tid + it * 512;           // float4 id, 8192 total
        int k = v >> 6;
        int n4 = (v & 63) * 4;
        const float* src = (n4 < 128) ? &W1[k * 128 + n4]
                                      : &W1[(128 + k) * 128 + (n4 - 128)];
        float4 val = *(const float4*)src;
        __half2 h01 = __floats2half2_rn(val.x, val.y);
        __half2 h23 = __floats2half2_rn(val.z, val.w);
        uint2 u = make_uint2(*(uint32_t*)&h01, *(uint32_t*)&h23);
        *(uint2*)&Bsm[k * BSH + n4] = u;
    }
    __syncthreads();

    float acc[2][8][4];
    #pragma unroll
    for (int mt = 0; mt < 2; ++mt)
        #pragma unroll
        for (int nt = 0; nt < 8; ++nt)
            #pragma unroll
            for (int q = 0; q < 4; ++q) acc[mt][nt][q] = 0.f;

    const int rbase = warpM * 32;
    const int cbase = warpN * 64;

    const uint32_t sb = smem_u32(smemc);
    uint32_t aB0 = sb + (uint32_t)(((rbase + (lane & 7) + ((lane >> 3) & 1) * 8) * ASH
                                    + ((lane >> 4) * 8)) * 2);
    uint32_t aB1 = aB0 + 16 * ASH * 2;
    uint32_t bB  = sb + A_BYTES + (uint32_t)((((lane & 15)) * BSH + cbase) * 2);

    #pragma unroll
    for (int ks = 0; ks < 8; ++ks) {      // K=128, 16 per step
        uint32_t a0[4], a1[4];
        LDM_X4(a0, aB0);
        LDM_X4(a1, aB1);
        #pragma unroll
        for (int nt = 0; nt < 8; ++nt) {
            uint32_t b[2];
            LDM_X2T(b, bB + nt * 16);
            MMA16(acc[0][nt], a0, b);
            MMA16(acc[1][nt], a1, b);
        }
        aB0 += 32;
        aB1 += 32;
        bB  += 16 * BSH * 2;
    }
    __syncthreads();   // done with Asm/Bsm; staging overlays them

    __half* XaS = (__half*)smemc;                   // [128][136]
    __half* XbS = (__half*)(smemc + XS_BYTES);      // [128][136]
    float*  red = (float*)(smemc + RED_OFF);        // [2 sel][2 half][128]

    // frags -> staging (b1 folded into Xb) + per-row w2 partial dots (raw)
    #pragma unroll
    for (int mt = 0; mt < 2; ++mt) {
        #pragma unroll
        for (int half = 0; half < 2; ++half) {
            int rloc = rbase + mt * 16 + half * 8 + gid;
            float p = 0.f;
            #pragma unroll
            for (int nt = 0; nt < 8; ++nt) {
                int col = cbase + nt * 8 + tg * 2;
                float c0 = acc[mt][nt][half * 2 + 0];
                float c1 = acc[mt][nt][half * 2 + 1];
                p = fmaf(c0, w2d[col], p);
                p = fmaf(c1, w2d[col + 1], p);
                if (col < 128) {
                    *(__half2*)&XaS[rloc * XS_STRIDE + col] = __floats2half2_rn(c0, c1);
                } else {
                    int cb = col - 128;
                    *(__half2*)&XbS[rloc * XS_STRIDE + cb] =
                        __floats2half2_rn(c0 + b1d[cb], c1 + b1d[cb + 1]);
                }
            }
            p += __shfl_xor_sync(0xffffffffu, p, 1);
            p += __shfl_xor_sync(0xffffffffu, p, 2);
            if (tg == 0)
                red[(warpN >> 1) * 256 + (warpN & 1) * 128 + rloc] = p;
        }
    }
    __syncthreads();

    // coalesced write-out: thread = row*4 + part; 4 uint4 chunks per table
    {
        int r = tid >> 2;
        int part = tid & 3;
        int row = row0 + r;
        if (row < nrows) {
            const uint4* sa4 = (const uint4*)((char*)XaS + (size_t)r * XS_STRIDE * 2);
            const uint4* sb4 = (const uint4*)((char*)XbS + (size_t)r * XS_STRIDE * 2);
            uint4* da4 = (uint4*)&g_Xa[(size_t)row * D];
            uint4* db4 = (uint4*)&g_Xb[(size_t)row * D];
            #pragma unroll
            for (int i = 0; i < 4; ++i) {
                int c = i * 4 + part;
                da4[c] = sa4[c];
                db4[c] = sb4[c];
            }
        }
        if (tid < 128) {
            int row2 = row0 + tid;
            if (row2 < nrows) {
                g_sa[row2] = red[tid] + red[128 + tid];
                g_sb[row2] = red[256 + tid] + red[384 + tid];
            }
        }
    }
}

// ---------------- gather: warp per dst node, 2 edges/iter, 8 cols/lane ----------------
__global__ void __launch_bounds__(256)
gather_kernel(const float* __restrict__ b1, float* __restrict__ out, int Nn)
{
    __shared__ float    exs[8][CAP + 2];
    __shared__ unsigned rcs[8][CAP + 2];
    int warp = (blockIdx.x * blockDim.x + threadIdx.x) >> 5;
    int lane = threadIdx.x & 31;
    int wl = threadIdx.x >> 5;
    if (warp >= Nn) return;

    int degn = min(g_deg[warp], CAP);
    const unsigned* base = &g_packed[warp * CAP];

    // pass 1: logits -> exp (lane-parallel); cache records; reduce denom
    float denom = 0.f;
    float sbn = g_sb[warp];
    for (int j0 = 0; j0 < degn; j0 += 32) {
        int j = j0 + lane;
        float ex = 0.f;
        if (j < degn) {
            unsigned rec = base[j];
            rcs[wl][j] = rec;
            int s = rec & 0xFFFF;
            int t = rec >> 16;
            float b = g_sa[s] + sbn + g_sr[t];
            b = b > 0.f ? b : SLOPE * b;
            ex = __expf(b);
            exs[wl][j] = ex;
        }
        denom += ex;
    }
    if (lane == 0) { exs[wl][degn] = 0.f; rcs[wl][degn] = 0u; }  // pad for odd degn
    #pragma unroll
    for (int o = 16; o > 0; o >>= 1)
        denom += __shfl_xor_sync(0xffffffffu, denom, o);
    float inv = (degn > 0) ? 1.f / denom : 0.f;
    for (int j = lane; j < degn; j += 32)
        exs[wl][j] *= inv;                 // pre-scale: alpha stored directly
    __syncwarp();

    // pass 2: lanes 0-15 -> edge j, lanes 16-31 -> edge j+1; 8 halves per lane
    int h  = lane >> 4;
    int cl = lane & 15;
    float accv[8];
    #pragma unroll
    for (int i = 0; i < 8; ++i) accv[i] = 0.f;

    for (int j = 0; j < degn; j += 2) {
        int je = j + h;
        unsigned rec = rcs[wl][je];
        float alpha = exs[wl][je];
        int s = rec & 0xFFFF;
        int t = rec >> 16;
        uint4 xa4 = *(const uint4*)&g_Xa[(size_t)s * D + cl * 8];
        uint4 rc4 = *(const uint4*)&g_RelC[t * D + cl * 8];
        const __half2* xh = (const __half2*)&xa4;
        const __half2* rh = (const __half2*)&rc4;
        #pragma unroll
        for (int q = 0; q < 4; ++q) {
            float2 f = __half22float2(__hadd2(xh[q], rh[q]));
            accv[q * 2 + 0] = fmaf(alpha, f.x, accv[q * 2 + 0]);
            accv[q * 2 + 1] = fmaf(alpha, f.y, accv[q * 2 + 1]);
        }
    }
    // combine half-warps
    #pragma unroll
    for (int i = 0; i < 8; ++i)
        accv[i] += __shfl_xor_sync(0xffffffffu, accv[i], 16);

    if (h == 0) {
        float o8[8];
        if (degn > 0) {
            uint4 xb4 = *(const uint4*)&g_Xb[(size_t)warp * D + cl * 8];  // includes b1
            const __half2* bh = (const __half2*)&xb4;
            #pragma unroll
            for (int q = 0; q < 4; ++q) {
                float2 fb = __half22float2(bh[q]);
                float v0 = accv[q * 2 + 0] + fb.x;
                float v1 = accv[q * 2 + 1] + fb.y;
                o8[q * 2 + 0] = v0 > 0.f ? v0 : SLOPE * v0;
                o8[q * 2 + 1] = v1 > 0.f ? v1 : SLOPE * v1;
            }
        } else {
            #pragma unroll
            for (int i = 0; i < 8; ++i) o8[i] = 0.f;
        }
        *(float4*)&out[(size_t)warp * D + cl * 8]     = *(float4*)&o8[0];
        *(float4*)&out[(size_t)warp * D + cl * 8 + 4] = *(float4*)&o8[4];
    }
}

// ---------------- launch ----------------
extern "C" void kernel_launch(void* const* d_in, const int* in_sizes, int n_in,
                              void* d_out, int out_size)
{
    const float* x   = (const float*)d_in[0];
    const float* rel = (const float*)d_in[1];
    const float* W1  = (const float*)d_in[2];
    const float* b1  = (const float*)d_in[3];
    const float* w2  = (const float*)d_in[4];
    const int*   ei  = (const int*)d_in[5];
    const int*   et  = (const int*)d_in[6];
    int Nn = in_sizes[0] / D;
    int Rr = in_sizes[1] / D;
    int Ee = in_sizes[5] / 2;
    float* out = (float*)d_out;

    int gb = (Nn + 127) / 128;
    int grid = gb + (Rr + 3) / 4;

    void* degp = nullptr;
    cudaGetSymbolAddress(&degp, g_deg);
    cudaMemsetAsync(degp, 0, (size_t)Nn * sizeof(int));

    cudaFuncSetAttribute(gemm_tc, cudaFuncAttributeMaxDynamicSharedMemorySize, SMEM_TOTAL);

    gemm_tc<<<grid, 512, SMEM_TOTAL>>>(x, rel, W1, b1, w2, ei, et, Nn, Rr, Ee, gb);
    gather_kernel<<<(Nn * 32 + 255) / 256, 256>>>(b1, out, Nn);
}

// round 12
// speedup vs baseline: 2.1775x; 1.0085x over previous
#include <cuda_runtime.h>
#include <cuda_fp16.h>
#include <cuda_bf16.h>
#include <cstdint>

#define NN 50000
#define EE 500000
#define RR 200
#define D 128
#define CAP 64
#define SLOPE 0.01f

// ---------------- scratch (static device globals; no allocation) ----------------
__device__ __half g_Xa[NN * D];       // x @ W1[0:128], fp16
__device__ __half g_Xb[NN * D];       // x @ W1[128:256] + b1, fp16
__device__ __half g_RelC[RR * D];     // rel @ W1[256:384], fp16
__device__ float  g_sa[NN];           // Xa . w2 (fp32 accum)
__device__ float  g_sb[NN];           // Xb . w2 (raw, without b1)
__device__ float  g_sr[RR];           // (RelC + b1) . w2
__device__ int      g_deg[NN];        // in-degree per dst (zeroed via memset node)
__device__ unsigned g_packed[NN * CAP]; // src | (et<<16); slots >= deg hold stale-but-valid records

__device__ __forceinline__ uint32_t smem_u32(const void* p) {
    uint32_t a;
    asm("{ .reg .u64 t; cvta.to.shared.u64 t, %1; cvt.u32.u64 %0, t; }" : "=r"(a) : "l"(p));
    return a;
}

#define LDM_X4(R, addr) \
    asm volatile("ldmatrix.sync.aligned.m8n8.x4.shared.b16 {%0,%1,%2,%3}, [%4];" \
        : "=r"((R)[0]), "=r"((R)[1]), "=r"((R)[2]), "=r"((R)[3]) : "r"(addr))
#define LDM_X2T(R, addr) \
    asm volatile("ldmatrix.sync.aligned.m8n8.x2.trans.shared.b16 {%0,%1}, [%2];" \
        : "=r"((R)[0]), "=r"((R)[1]) : "r"(addr))
#define MMA16(C, A, B) \
    asm volatile("mma.sync.aligned.m16n8k16.row.col.f32.f16.f16.f32 " \
        "{%0,%1,%2,%3}, {%4,%5,%6,%7}, {%8,%9}, {%0,%1,%2,%3};" \
        : "+f"((C)[0]), "+f"((C)[1]), "+f"((C)[2]), "+f"((C)[3]) \
        : "r"((A)[0]), "r"((A)[1]), "r"((A)[2]), "r"((A)[3]), "r"((B)[0]), "r"((B)[1]))

// ---------------- smem layout (gemm) ----------------
#define ASH 136
#define BSH 264
#define A_BYTES (128 * ASH * 2)
#define B_BYTES (128 * BSH * 2)
#define XS_STRIDE 136
#define XS_BYTES (128 * XS_STRIDE * 2)
#define W2D_OFF (A_BYTES + B_BYTES)
#define B1D_OFF (W2D_OFF + 256 * 4)
#define RED_OFF (B1D_OFF + 128 * 4)
#define SMEM_TOTAL (RED_OFF + 512 * 4)

// ---------------- fused: edge fill + fp16 mma GEMM + relc ----------------
__global__ void __launch_bounds__(512, 1)
gemm_tc(const float* __restrict__ x, const float* __restrict__ rel,
        const float* __restrict__ W1, const float* __restrict__ b1,
        const float* __restrict__ w2,
        const int* __restrict__ ei, const int* __restrict__ et,
        int nrows, int Rr, int Ee, int gb)
{
    extern __shared__ float smem[];
    char* smemc = (char*)smem;
    const int tid = threadIdx.x;          // 512

    // ======== edge-fill prologue (all blocks) ========
    {
        int stride = gridDim.x * 512;
        for (int e = blockIdx.x * 512 + tid; e < Ee; e += stride) {
            int d = ei[Ee + e];
            int pos = atomicAdd(&g_deg[d], 1);
            if (pos < CAP)
                g_packed[d * CAP + pos] = (unsigned)ei[e] | ((unsigned)et[e] << 16);
        }
    }

    // ======== relation blocks ========
    if (blockIdx.x >= gb) {
        int rb = blockIdx.x - gb;
        int grp = tid >> 7;               // 0..3
        int j = tid & 127;
        int rr = rb * 4 + grp;
        float* rs = smem + grp * 128;     // [4][128]
        float* rp = smem + 512;           // [16] warp partials
        if (rr < Rr) rs[j] = rel[rr * D + j];
        __syncthreads();
        if (rr < Rr) {
            const float* Wc = W1 + 256 * 128;
            float acc = 0.f;
            #pragma unroll 8
            for (int k = 0; k < 128; ++k)
                acc = fmaf(rs[k], Wc[k * 128 + j], acc);
            g_RelC[rr * D + j] = __float2half_rn(acc);
            float p = (acc + b1[j]) * w2[j];
            #pragma unroll
            for (int o = 16; o > 0; o >>= 1)
                p += __shfl_xor_sync(0xffffffffu, p, o);
            if ((j & 31) == 0) rp[grp * 4 + (j >> 5)] = p;
        }
        __syncthreads();
        if (j == 0 && rr < Rr)
            g_sr[rr] = rp[grp * 4] + rp[grp * 4 + 1] + rp[grp * 4 + 2] + rp[grp * 4 + 3];
        return;
    }

    // ======== GEMM blocks ========
    __half* Asm = (__half*)smemc;
    __half* Bsm = (__half*)(smemc + A_BYTES);
    float*  w2d = (float*)(smemc + W2D_OFF);
    float*  b1d = (float*)(smemc + B1D_OFF);

    const int wid  = tid >> 5;
    const int lane = tid & 31;
    const int gid  = lane >> 2;
    const int tg   = lane & 3;
    const int warpM = wid & 3;
    const int warpN = wid >> 2;
    const int row0 = blockIdx.x * 128;

    if (tid < 256) w2d[tid] = w2[tid & 127];
    else if (tid < 384) b1d[tid - 256] = b1[tid - 256];

    // fill A (fp16 halves), zero-pad tail rows
    #pragma unroll
    for (int it = 0; it < 8; ++it) {
        int v = tid + it * 512;
        int r = v >> 5;
        int c = (v & 31) * 4;
        float4 val = make_float4(0.f, 0.f, 0.f, 0.f);
        int grow = row0 + r;
        if (grow < nrows) val = *(const float4*)&x[(size_t)grow * D + c];
        __half2 h01 = __floats2half2_rn(val.x, val.y);
        __half2 h23 = __floats2half2_rn(val.z, val.w);
        uint2 u = make_uint2(*(uint32_t*)&h01, *(uint32_t*)&h23);
        *(uint2*)&Asm[r * ASH + c] = u;
    }
    // fill B halves [k][n]
    #pragma unroll
    for (int it = 0; it < 16; ++it) {
        int v = tid + it * 512;
        int k = v >> 6;
        int n4 = (v & 63) * 4;
        const float* src = (n4 < 128) ? &W1[k * 128 + n4]
                                      : &W1[(128 + k) * 128 + (n4 - 128)];
        float4 val = *(const float4*)src;
        __half2 h01 = __floats2half2_rn(val.x, val.y);
        __half2 h23 = __floats2half2_rn(val.z, val.w);
        uint2 u = make_uint2(*(uint32_t*)&h01, *(uint32_t*)&h23);
        *(uint2*)&Bsm[k * BSH + n4] = u;
    }
    __syncthreads();

    float acc[2][8][4];
    #pragma unroll
    for (int mt = 0; mt < 2; ++mt)
        #pragma unroll
        for (int nt = 0; nt < 8; ++nt)
            #pragma unroll
            for (int q = 0; q < 4; ++q) acc[mt][nt][q] = 0.f;

    const int rbase = warpM * 32;
    const int cbase = warpN * 64;

    const uint32_t sb = smem_u32(smemc);
    uint32_t aB0 = sb + (uint32_t)(((rbase + (lane & 7) + ((lane >> 3) & 1) * 8) * ASH
                                    + ((lane >> 4) * 8)) * 2);
    uint32_t aB1 = aB0 + 16 * ASH * 2;
    uint32_t bB  = sb + A_BYTES + (uint32_t)((((lane & 15)) * BSH + cbase) * 2);

    #pragma unroll
    for (int ks = 0; ks < 8; ++ks) {
        uint32_t a0[4], a1[4];
        LDM_X4(a0, aB0);
        LDM_X4(a1, aB1);
        #pragma unroll
        for (int nt = 0; nt < 8; ++nt) {
            uint32_t b[2];
            LDM_X2T(b, bB + nt * 16);
            MMA16(acc[0][nt], a0, b);
            MMA16(acc[1][nt], a1, b);
        }
        aB0 += 32;
        aB1 += 32;
        bB  += 16 * BSH * 2;
    }
    __syncthreads();

    __half* XaS = (__half*)smemc;
    __half* XbS = (__half*)(smemc + XS_BYTES);
    float*  red = (float*)(smemc + RED_OFF);

    #pragma unroll
    for (int mt = 0; mt < 2; ++mt) {
        #pragma unroll
        for (int half = 0; half < 2; ++half) {
            int rloc = rbase + mt * 16 + half * 8 + gid;
            float p = 0.f;
            #pragma unroll
            for (int nt = 0; nt < 8; ++nt) {
                int col = cbase + nt * 8 + tg * 2;
                float c0 = acc[mt][nt][half * 2 + 0];
                float c1 = acc[mt][nt][half * 2 + 1];
                p = fmaf(c0, w2d[col], p);
                p = fmaf(c1, w2d[col + 1], p);
                if (col < 128) {
                    *(__half2*)&XaS[rloc * XS_STRIDE + col] = __floats2half2_rn(c0, c1);
                } else {
                    int cb = col - 128;
                    *(__half2*)&XbS[rloc * XS_STRIDE + cb] =
                        __floats2half2_rn(c0 + b1d[cb], c1 + b1d[cb + 1]);
                }
            }
            p += __shfl_xor_sync(0xffffffffu, p, 1);
            p += __shfl_xor_sync(0xffffffffu, p, 2);
            if (tg == 0)
                red[(warpN >> 1) * 256 + (warpN & 1) * 128 + rloc] = p;
        }
    }
    __syncthreads();

    {
        int r = tid >> 2;
        int part = tid & 3;
        int row = row0 + r;
        if (row < nrows) {
            const uint4* sa4 = (const uint4*)((char*)XaS + (size_t)r * XS_STRIDE * 2);
            const uint4* sb4 = (const uint4*)((char*)XbS + (size_t)r * XS_STRIDE * 2);
            uint4* da4 = (uint4*)&g_Xa[(size_t)row * D];
            uint4* db4 = (uint4*)&g_Xb[(size_t)row * D];
            #pragma unroll
            for (int i = 0; i < 4; ++i) {
                int c = i * 4 + part;
                da4[c] = sa4[c];
                db4[c] = sb4[c];
            }
        }
        if (tid < 128) {
            int row2 = row0 + tid;
            if (row2 < nrows) {
                g_sa[row2] = red[tid] + red[128 + tid];
                g_sb[row2] = red[256 + tid] + red[384 + tid];
            }
        }
    }
}

// ---------------- gather: warp per dst node, smem-free shuffle design ----------------
// Slots >= deg in g_packed hold stale-but-valid records (or zeros on run 1), so
// all loads issue unconditionally in parallel; masking happens at ex.
#define GBODY(r_, al)                                                        \
    {                                                                        \
        int s_ = (r_) & 0xFFFF, t_ = (r_) >> 16;                             \
        uint4 xa4 = *(const uint4*)&g_Xa[(size_t)s_ * D + cl * 8];           \
        uint4 rc4 = *(const uint4*)&g_RelC[t_ * D + cl * 8];                 \
        const __half2* xh = (const __half2*)&xa4;                            \
        const __half2* rh = (const __half2*)&rc4;                            \
        _Pragma("unroll")                                                    \
        for (int q = 0; q < 4; ++q) {                                        \
            float2 f = __half22float2(__hadd2(xh[q], rh[q]));                \
            accv[q * 2 + 0] = fmaf((al), f.x, accv[q * 2 + 0]);              \
            accv[q * 2 + 1] = fmaf((al), f.y, accv[q * 2 + 1]);              \
        }                                                                    \
    }

__global__ void __launch_bounds__(256)
gather_kernel(float* __restrict__ out, int Nn)
{
    const unsigned F = 0xffffffffu;
    int warp = (blockIdx.x * blockDim.x + threadIdx.x) >> 5;
    int lane = threadIdx.x & 31;
    if (warp >= Nn) return;

    const unsigned* base = &g_packed[warp * CAP];

    // parallel, unconditional warp-start loads
    unsigned rec = __ldg(&base[lane]);
    int degn = min(g_deg[warp], CAP);
    float sbn = g_sb[warp];

    // chunk 0 logits (lane-parallel)
    int s0 = rec & 0xFFFF, t0 = rec >> 16;
    float b0 = g_sa[s0] + sbn + g_sr[t0];
    b0 = b0 > 0.f ? b0 : SLOPE * b0;
    float ex = (lane < degn) ? __expf(b0) : 0.f;

    // chunk 1 (deg in (32,64]) — virtually never taken, kept for exactness
    unsigned rec2 = 0u;
    float ex2 = 0.f;
    if (degn > 32) {
        rec2 = __ldg(&base[32 + lane]);
        int s1 = rec2 & 0xFFFF, t1 = rec2 >> 16;
        float b1v = g_sa[s1] + sbn + g_sr[t1];
        b1v = b1v > 0.f ? b1v : SLOPE * b1v;
        ex2 = (32 + lane < degn) ? __expf(b1v) : 0.f;
    }

    float denom = ex + ex2;
    #pragma unroll
    for (int o = 16; o > 0; o >>= 1)
        denom += __shfl_xor_sync(F, denom, o);
    float inv = (degn > 0) ? 1.f / denom : 0.f;
    float a1 = ex * inv;
    float a2 = ex2 * inv;

    // pass 2: lanes 0-15 -> edge j, lanes 16-31 -> edge j+1; 8 cols/lane
    int h  = lane >> 4;
    int cl = lane & 15;
    float accv[8];
    #pragma unroll
    for (int i = 0; i < 8; ++i) accv[i] = 0.f;

    if (degn <= 32) {
        #pragma unroll 2
        for (int j = 0; j < degn; j += 2) {
            int je = j + h;                              // je <= 31; odd-degn pad has alpha 0
            unsigned r_ = __shfl_sync(F, rec, je);
            float al = __shfl_sync(F, a1, je);
            GBODY(r_, al);
        }
    } else {
        for (int j = 0; j < degn; j += 2) {
            int je = j + h;
            int sl = je & 31;
            unsigned rA = __shfl_sync(F, rec,  sl);
            unsigned rB = __shfl_sync(F, rec2, sl);
            float aA = __shfl_sync(F, a1, sl);
            float aB = __shfl_sync(F, a2, sl);
            unsigned r_ = (je < 32) ? rA : rB;
            float al = (je < 32) ? aA : aB;
            GBODY(r_, al);
        }
    }

    // combine half-warps
    #pragma unroll
    for (int i = 0; i < 8; ++i)
        accv[i] += __shfl_xor_sync(F, accv[i], 16);

    if (h == 0) {
        float o8[8];
        if (degn > 0) {
            uint4 xb4 = *(const uint4*)&g_Xb[(size_t)warp * D + cl * 8];  // includes b1
            const __half2* bh = (const __half2*)&xb4;
            #pragma unroll
            for (int q = 0; q < 4; ++q) {
                float2 fb = __half22float2(bh[q]);
                float v0 = accv[q * 2 + 0] + fb.x;
                float v1 = accv[q * 2 + 1] + fb.y;
                o8[q * 2 + 0] = v0 > 0.f ? v0 : SLOPE * v0;
                o8[q * 2 + 1] = v1 > 0.f ? v1 : SLOPE * v1;
            }
        } else {
            #pragma unroll
            for (int i = 0; i < 8; ++i) o8[i] = 0.f;
        }
        *(float4*)&out[(size_t)warp * D + cl * 8]     = *(float4*)&o8[0];
        *(float4*)&out[(size_t)warp * D + cl * 8 + 4] = *(float4*)&o8[4];
    }
}

// ---------------- launch ----------------
extern "C" void kernel_launch(void* const* d_in, const int* in_sizes, int n_in,
                              void* d_out, int out_size)
{
    const float* x   = (const float*)d_in[0];
    const float* rel = (const float*)d_in[1];
    const float* W1  = (const float*)d_in[2];
    const float* b1  = (const float*)d_in[3];
    const float* w2  = (const float*)d_in[4];
    const int*   ei  = (const int*)d_in[5];
    const int*   et  = (const int*)d_in[6];
    int Nn = in_sizes[0] / D;
    int Rr = in_sizes[1] / D;
    int Ee = in_sizes[5] / 2;
    float* out = (float*)d_out;

    int gb = (Nn + 127) / 128;
    int grid = gb + (Rr + 3) / 4;

    void* degp = nullptr;
    cudaGetSymbolAddress(&degp, g_deg);
    cudaMemsetAsync(degp, 0, (size_t)Nn * sizeof(int));

    cudaFuncSetAttribute(gemm_tc, cudaFuncAttributeMaxDynamicSharedMemorySize, SMEM_TOTAL);

    gemm_tc<<<grid, 512, SMEM_TOTAL>>>(x, rel, W1, b1, w2, ei, et, Nn, Rr, Ee, gb);
    gather_kernel<<<(Nn * 32 + 255) / 256, 256>>>(out, Nn);
}